// round 1
// baseline (speedup 1.0000x reference)
#include <cuda_runtime.h>
#include <math.h>

#define B_  128
#define L_  512
#define N_  1023
#define T_  511
#define D_  256
#define V_  50000
#define C_  511
#define EPSF 1e-6f

// Scratch: node vectors v[B][N][D], fp32 (134 MB)
__device__ float g_v[(size_t)B_ * N_ * D_];

// ---------------------------------------------------------------------------
// Stage 0: zero the node buffer
// ---------------------------------------------------------------------------
__global__ void k_zero(int n4) {
    float4* p = reinterpret_cast<float4*>(g_v);
    int i = blockIdx.x * blockDim.x + threadIdx.x;
    int stride = gridDim.x * blockDim.x;
    float4 z = make_float4(0.f, 0.f, 0.f, 0.f);
    for (; i < n4; i += stride) p[i] = z;
}

// ---------------------------------------------------------------------------
// Stage 1a: scatter leaf embeddings (unnormalized) into g_v
// grid: B*L blocks, 64 threads (D/4 float4 per block)
// ---------------------------------------------------------------------------
__global__ void k_scatter(const int* __restrict__ leaf,   // [B,L,2]
                          const int* __restrict__ cmask,  // [B,L]
                          const float* __restrict__ emb)  // [V,D]
{
    int bl = blockIdx.x;
    if (cmask[bl] == 0) return;
    int idx = leaf[2 * bl + 0];
    int vid = leaf[2 * bl + 1];
    if ((unsigned)idx >= (unsigned)N_) return;   // mode='drop'
    int b = bl / L_;
    const float4* src = reinterpret_cast<const float4*>(emb + (size_t)vid * D_);
    float4* dst = reinterpret_cast<float4*>(g_v + ((size_t)b * N_ + idx) * D_);
    dst[threadIdx.x] = src[threadIdx.x];
}

// ---------------------------------------------------------------------------
// Stage 1b: L2-normalize every node vector in place
// grid: B*N blocks, 64 threads
// ---------------------------------------------------------------------------
__global__ void k_norm() {
    size_t node = blockIdx.x;
    float4* p = reinterpret_cast<float4*>(g_v + node * (size_t)D_);
    float4 x = p[threadIdx.x];
    float s = x.x * x.x + x.y * x.y + x.z * x.z + x.w * x.w;
    #pragma unroll
    for (int o = 16; o; o >>= 1) s += __shfl_xor_sync(0xffffffffu, s, o);
    __shared__ float sh[2];
    if ((threadIdx.x & 31) == 0) sh[threadIdx.x >> 5] = s;
    __syncthreads();
    float tot = sh[0] + sh[1];
    float sc = 1.f / (sqrtf(tot) + EPSF);
    x.x *= sc; x.y *= sc; x.z *= sc; x.w *= sc;
    p[threadIdx.x] = x;
}

// ---------------------------------------------------------------------------
// Stage 2: sequential tree composition. One block per batch, 128 threads.
// type 0: no-op (writes v[b,0] <- v[b,0])
// type 1: v[b,p] <- v[b,l]
// type 2: v[b,p] <- normalize(circ_corr(v[b,l], v[b,r]))
//         c[k] = sum_j a[j] * b[(j+k) mod D]
// ---------------------------------------------------------------------------
__global__ void __launch_bounds__(128) k_compose(const int* __restrict__ cinfo)
{
    int b = blockIdx.x;
    float* v = g_v + (size_t)b * N_ * D_;
    const int4* info = reinterpret_cast<const int4*>(cinfo + (size_t)b * T_ * 4);

    __shared__ __align__(16) float sa[D_];
    __shared__ __align__(16) float sb[2 * D_];
    __shared__ float sred[4];

    int tid = threadIdx.x;
    int k2 = 2 * tid;

    for (int t = 0; t < T_; ++t) {
        int4 ci = __ldg(&info[t]);
        int ty = ci.x, p = ci.y, l = ci.z, r = ci.w;

        if (ty == 1) {
            float2 x = *reinterpret_cast<const float2*>(v + (size_t)l * D_ + k2);
            *reinterpret_cast<float2*>(v + (size_t)p * D_ + k2) = x;
            __syncthreads();
        } else if (ty == 2) {
            float2 a2 = *reinterpret_cast<const float2*>(v + (size_t)l * D_ + k2);
            float2 b2 = *reinterpret_cast<const float2*>(v + (size_t)r * D_ + k2);
            *reinterpret_cast<float2*>(sa + k2) = a2;
            *reinterpret_cast<float2*>(sb + k2) = b2;
            *reinterpret_cast<float2*>(sb + D_ + k2) = b2;
            __syncthreads();

            // sliding-window correlation: thread computes c[2t], c[2t+1]
            float2 w = *reinterpret_cast<const float2*>(sb + k2);
            float c0a = 0.f, c0b = 0.f, c1a = 0.f, c1b = 0.f;
            #pragma unroll
            for (int j = 0; j < D_; j += 4) {
                float4 aj = *reinterpret_cast<const float4*>(sa + j);
                float2 n1 = *reinterpret_cast<const float2*>(sb + j + 2 + k2);
                float2 n2 = *reinterpret_cast<const float2*>(sb + j + 4 + k2);
                c0a = fmaf(aj.x, w.x,  c0a);
                c0a = fmaf(aj.y, w.y,  c0a);
                c0b = fmaf(aj.z, n1.x, c0b);
                c0b = fmaf(aj.w, n1.y, c0b);
                c1a = fmaf(aj.x, w.y,  c1a);
                c1a = fmaf(aj.y, n1.x, c1a);
                c1b = fmaf(aj.z, n1.y, c1b);
                c1b = fmaf(aj.w, n2.x, c1b);
                w = n2;
            }
            float c0 = c0a + c0b;
            float c1 = c1a + c1b;

            float s = c0 * c0 + c1 * c1;
            #pragma unroll
            for (int o = 16; o; o >>= 1) s += __shfl_xor_sync(0xffffffffu, s, o);
            if ((tid & 31) == 0) sred[tid >> 5] = s;
            __syncthreads();
            float tot = sred[0] + sred[1] + sred[2] + sred[3];
            float sc = 1.f / (sqrtf(tot) + EPSF);

            float2 o2 = make_float2(c0 * sc, c1 * sc);
            *reinterpret_cast<float2*>(v + (size_t)p * D_ + k2) = o2;
            __syncthreads();
        }
        // ty == 0: provable no-op
    }
}

// ---------------------------------------------------------------------------
// Stage 3: out[m, c] = dot(v[m,:], W[c,:]) + bias[c]
// M = B*N = 130944 (exactly 1023 tiles of 128), N = C_ = 511, K = 256
// Tile: BM=128, BN=64, BK=16; 256 threads; 8x4 per thread.
// ---------------------------------------------------------------------------
#define BM 128
#define BN 64
#define BK 16

__global__ void __launch_bounds__(256, 2)
k_gemm(const float* __restrict__ Wt,     // [C, D]
       const float* __restrict__ bias,   // [C]
       float* __restrict__ out)          // [M, C]
{
    __shared__ __align__(16) float As[BK][BM + 4];   // stride 132 floats (16B-aligned rows)
    __shared__ __align__(16) float Bs[BK][BN + 4];   // stride 68 floats  (16B-aligned rows)

    int m0 = blockIdx.x * BM;
    int n0 = blockIdx.y * BN;
    int tid = threadIdx.x;
    int tx = tid & 15;        // N direction (16 * 4 = 64)
    int tyy = tid >> 4;       // M direction (16 * 8 = 128)

    const float* A = g_v + (size_t)m0 * D_;

    float acc[8][4];
    #pragma unroll
    for (int i = 0; i < 8; ++i)
        #pragma unroll
        for (int j = 0; j < 4; ++j) acc[i][j] = 0.f;

    int arow = tid >> 1;           // 0..127
    int akq  = (tid & 1) * 2;      // 0 or 2; loads quads akq, akq+1
    int brow = tid >> 2;           // 0..63
    int bkq  = tid & 3;            // 0..3

    for (int k0 = 0; k0 < D_; k0 += BK) {
        // A tile: 128 rows x 16 k; 2 float4 per thread
        #pragma unroll
        for (int u = 0; u < 2; ++u) {
            float4 a4 = *reinterpret_cast<const float4*>(
                A + (size_t)arow * D_ + k0 + (akq + u) * 4);
            As[(akq + u) * 4 + 0][arow] = a4.x;
            As[(akq + u) * 4 + 1][arow] = a4.y;
            As[(akq + u) * 4 + 2][arow] = a4.z;
            As[(akq + u) * 4 + 3][arow] = a4.w;
        }
        // B tile: 64 rows x 16 k; 1 float4 per thread (guard row >= C_)
        {
            int n = n0 + brow;
            float4 b4 = (n < C_)
                ? *reinterpret_cast<const float4*>(Wt + (size_t)n * D_ + k0 + bkq * 4)
                : make_float4(0.f, 0.f, 0.f, 0.f);
            Bs[bkq * 4 + 0][brow] = b4.x;
            Bs[bkq * 4 + 1][brow] = b4.y;
            Bs[bkq * 4 + 2][brow] = b4.z;
            Bs[bkq * 4 + 3][brow] = b4.w;
        }
        __syncthreads();

        #pragma unroll
        for (int kk = 0; kk < BK; ++kk) {
            float4 af0 = *reinterpret_cast<const float4*>(&As[kk][tyy * 8 + 0]);
            float4 af1 = *reinterpret_cast<const float4*>(&As[kk][tyy * 8 + 4]);
            float4 bf  = *reinterpret_cast<const float4*>(&Bs[kk][tx * 4]);
            float af[8] = {af0.x, af0.y, af0.z, af0.w, af1.x, af1.y, af1.z, af1.w};
            float bfr[4] = {bf.x, bf.y, bf.z, bf.w};
            #pragma unroll
            for (int i = 0; i < 8; ++i)
                #pragma unroll
                for (int j = 0; j < 4; ++j)
                    acc[i][j] = fmaf(af[i], bfr[j], acc[i][j]);
        }
        __syncthreads();
    }

    // epilogue
    float bv[4];
    #pragma unroll
    for (int j = 0; j < 4; ++j) {
        int n = n0 + tx * 4 + j;
        bv[j] = (n < C_) ? bias[n] : 0.f;
    }
    #pragma unroll
    for (int i = 0; i < 8; ++i) {
        int m = m0 + tyy * 8 + i;
        float* orow = out + (size_t)m * C_;
        #pragma unroll
        for (int j = 0; j < 4; ++j) {
            int n = n0 + tx * 4 + j;
            if (n < C_) orow[n] = acc[i][j] + bv[j];
        }
    }
}

// ---------------------------------------------------------------------------
// launcher
// ---------------------------------------------------------------------------
extern "C" void kernel_launch(void* const* d_in, const int* in_sizes, int n_in,
                              void* d_out, int out_size)
{
    // inputs: num_node, leaf_content_id, content_mask, composition_info,
    //         emb_weight, lin_weight, lin_bias
    const int*   leaf  = (const int*)  d_in[1];
    const int*   cmask = (const int*)  d_in[2];
    const int*   cinfo = (const int*)  d_in[3];
    const float* emb   = (const float*)d_in[4];
    const float* W     = (const float*)d_in[5];
    const float* bias  = (const float*)d_in[6];
    float* out = (float*)d_out;

    int n4 = (B_ * N_ * D_) / 4;
    k_zero<<<8192, 256>>>(n4);
    k_scatter<<<B_ * L_, D_ / 4>>>(leaf, cmask, emb);
    k_norm<<<B_ * N_, D_ / 4>>>();
    k_compose<<<B_, 128>>>(cinfo);
    dim3 ggrid(1023, (C_ + BN - 1) / BN);   // 1023 x 8
    k_gemm<<<ggrid, 256>>>(W, bias, out);
}

// round 6
// speedup vs baseline: 1.2479x; 1.2479x over previous
#include <cuda_runtime.h>
#include <cuda_bf16.h>
#include <mma.h>
#include <math.h>
#include <stdint.h>

using namespace nvcuda;

#define B_  128
#define L_  512
#define N_  1023
#define T_  511
#define D_  256
#define V_  50000
#define C_  511
#define EPSF 1e-6f

#define M_TOT (B_ * N_)          // 130944

// Scratch
__device__ float g_v[(size_t)B_ * N_ * D_];                        // 134 MB
__device__ __align__(16) __nv_bfloat16 g_Ah[(size_t)M_TOT * D_];   // 67 MB
__device__ __align__(16) __nv_bfloat16 g_Al[(size_t)M_TOT * D_];   // 67 MB
__device__ __align__(16) __nv_bfloat16 g_Wh[512 * 256];            // W hi (row 511 zero)
__device__ __align__(16) __nv_bfloat16 g_Wl[512 * 256];            // W lo

// ---------------------------------------------------------------------------
// Stage 0: zero node buffer
// ---------------------------------------------------------------------------
__global__ void k_zero(int n4) {
    float4* p = reinterpret_cast<float4*>(g_v);
    int i = blockIdx.x * blockDim.x + threadIdx.x;
    int stride = gridDim.x * blockDim.x;
    float4 z = make_float4(0.f, 0.f, 0.f, 0.f);
    for (; i < n4; i += stride) p[i] = z;
}

// ---------------------------------------------------------------------------
// Stage 1: scatter leaf embeddings, L2-normalized, into g_v (fused)
// ---------------------------------------------------------------------------
__global__ void k_scatter_norm(const int* __restrict__ leaf,
                               const int* __restrict__ cmask,
                               const float* __restrict__ emb) {
    int bl = blockIdx.x;
    if (cmask[bl] == 0) return;
    int idx = leaf[2 * bl + 0];
    int vid = leaf[2 * bl + 1];
    if ((unsigned)idx >= (unsigned)N_) return;
    int b = bl / L_;
    const float4* src = reinterpret_cast<const float4*>(emb + (size_t)vid * D_);
    float4 x = src[threadIdx.x];
    float s = x.x * x.x + x.y * x.y + x.z * x.z + x.w * x.w;
    #pragma unroll
    for (int o = 16; o; o >>= 1) s += __shfl_xor_sync(0xffffffffu, s, o);
    __shared__ float sh[2];
    if ((threadIdx.x & 31) == 0) sh[threadIdx.x >> 5] = s;
    __syncthreads();
    float sc = 1.f / (sqrtf(sh[0] + sh[1]) + EPSF);
    x.x *= sc; x.y *= sc; x.z *= sc; x.w *= sc;
    float4* dst = reinterpret_cast<float4*>(g_v + ((size_t)b * N_ + idx) * D_);
    dst[threadIdx.x] = x;
}

// ---------------------------------------------------------------------------
// Stage 1b: convert W to bf16 hi/lo (512 rows, row 511 zero)
// ---------------------------------------------------------------------------
__global__ void k_convW(const float* __restrict__ W) {
    int row = blockIdx.x;
    int c = threadIdx.x * 4;
    __nv_bfloat16 h[4], l[4];
    if (row < C_) {
        float4 w = *reinterpret_cast<const float4*>(W + (size_t)row * D_ + c);
        float f[4] = {w.x, w.y, w.z, w.w};
        #pragma unroll
        for (int i = 0; i < 4; ++i) {
            h[i] = __float2bfloat16(f[i]);
            l[i] = __float2bfloat16(f[i] - __bfloat162float(h[i]));
        }
    } else {
        #pragma unroll
        for (int i = 0; i < 4; ++i) { h[i] = __float2bfloat16(0.f); l[i] = h[i]; }
    }
    #pragma unroll
    for (int i = 0; i < 4; ++i) {
        g_Wh[(size_t)row * D_ + c + i] = h[i];
        g_Wl[(size_t)row * D_ + c + i] = l[i];
    }
}

// ---------------------------------------------------------------------------
// Stage 2: sequential tree composition. 1 block/batch, 256 threads (8 warps).
// Output pair c[2q],c[2q+1] computed by two threads (split j-range).
// ---------------------------------------------------------------------------
__global__ void __launch_bounds__(256) k_compose(const int* __restrict__ cinfo)
{
    int b = blockIdx.x;
    float* v = g_v + (size_t)b * N_ * D_;
    const int4* info = reinterpret_cast<const int4*>(cinfo + (size_t)b * T_ * 4);

    __shared__ __align__(16) float sa[D_];
    __shared__ __align__(16) float sb[2 * D_];
    __shared__ float2 pp[128];
    __shared__ float sred[8];

    int tid = threadIdx.x;
    int lid = tid & 31;
    int wid = tid >> 5;
    int kk = (tid & 127) * 2;     // output pair
    int j0 = (tid >> 7) * 128;    // j half

    for (int t = 0; t < T_; ++t) {
        int4 ci = __ldg(&info[t]);
        int ty = ci.x, p = ci.y, l = ci.z, r = ci.w;

        if (ty == 1) {
            v[(size_t)p * D_ + tid] = v[(size_t)l * D_ + tid];
            __syncthreads();
        } else if (ty == 2) {
            float av = v[(size_t)l * D_ + tid];
            float bv = v[(size_t)r * D_ + tid];
            sa[tid] = av;
            sb[tid] = bv;
            sb[tid + 256] = bv;
            __syncthreads();

            float2 w = *reinterpret_cast<const float2*>(sb + j0 + kk);
            float c0a = 0.f, c0b = 0.f, c1a = 0.f, c1b = 0.f;
            #pragma unroll
            for (int j = j0; j < j0 + 128; j += 4) {
                float4 aj = *reinterpret_cast<const float4*>(sa + j);
                float2 n1 = *reinterpret_cast<const float2*>(sb + j + 2 + kk);
                float2 n2 = *reinterpret_cast<const float2*>(sb + j + 4 + kk);
                c0a = fmaf(aj.x, w.x,  c0a);
                c0a = fmaf(aj.y, w.y,  c0a);
                c0b = fmaf(aj.z, n1.x, c0b);
                c0b = fmaf(aj.w, n1.y, c0b);
                c1a = fmaf(aj.x, w.y,  c1a);
                c1a = fmaf(aj.y, n1.x, c1a);
                c1b = fmaf(aj.z, n1.y, c1b);
                c1b = fmaf(aj.w, n2.x, c1b);
                w = n2;
            }
            float c0 = c0a + c0b;
            float c1 = c1a + c1b;

            if (tid >= 128) pp[tid & 127] = make_float2(c0, c1);
            __syncthreads();

            float s = 0.f;
            if (tid < 128) {
                float2 q = pp[tid];
                c0 += q.x; c1 += q.y;
                s = c0 * c0 + c1 * c1;
            }
            #pragma unroll
            for (int o = 16; o; o >>= 1) s += __shfl_xor_sync(0xffffffffu, s, o);
            if (lid == 0) sred[wid] = s;
            __syncthreads();
            float tot = sred[0] + sred[1] + sred[2] + sred[3];
            if (tid < 128) {
                float sc = 1.f / (sqrtf(tot) + EPSF);
                *reinterpret_cast<float2*>(v + (size_t)p * D_ + kk) =
                    make_float2(c0 * sc, c1 * sc);
            }
            __syncthreads();
        }
        // ty == 0: no-op
    }
}

// ---------------------------------------------------------------------------
// Stage 2b: convert composed node vectors fp32 -> bf16 hi/lo
// ---------------------------------------------------------------------------
__global__ void k_convA(int n4) {
    const float4* src = reinterpret_cast<const float4*>(g_v);
    uint2* ah = reinterpret_cast<uint2*>(g_Ah);
    uint2* al = reinterpret_cast<uint2*>(g_Al);
    int i = blockIdx.x * blockDim.x + threadIdx.x;
    int stride = gridDim.x * blockDim.x;
    for (; i < n4; i += stride) {
        float4 x = src[i];
        __nv_bfloat16 h0 = __float2bfloat16(x.x), h1 = __float2bfloat16(x.y);
        __nv_bfloat16 h2 = __float2bfloat16(x.z), h3 = __float2bfloat16(x.w);
        __nv_bfloat16 l0 = __float2bfloat16(x.x - __bfloat162float(h0));
        __nv_bfloat16 l1 = __float2bfloat16(x.y - __bfloat162float(h1));
        __nv_bfloat16 l2 = __float2bfloat16(x.z - __bfloat162float(h2));
        __nv_bfloat16 l3 = __float2bfloat16(x.w - __bfloat162float(h3));
        __nv_bfloat162 hA = {h0, h1}, hB = {h2, h3}, lA = {l0, l1}, lB = {l2, l3};
        ah[i] = make_uint2(*reinterpret_cast<uint32_t*>(&hA),
                           *reinterpret_cast<uint32_t*>(&hB));
        al[i] = make_uint2(*reinterpret_cast<uint32_t*>(&lA),
                           *reinterpret_cast<uint32_t*>(&lB));
    }
}

// ---------------------------------------------------------------------------
// Stage 3: WMMA bf16-split GEMM.
// out[m, n] = sum_k v[m,k] * W[n,k] + bias[n]
// Grid (1023, 4): CTA = 128 M x 128 N.  8 warps, warp = 32 M x 64 N.
// K chunked by 64.  acc += Ah*Bh + Ah*Bl + Al*Bh.
// SLD = 80 elements (160 B): every wmma row pointer 32-byte aligned.
// ---------------------------------------------------------------------------
#define SLD 80      // bf16 smem leading dim (160 B rows, 256-bit aligned)
#define TLD 136     // f32 epilogue leading dim (544 B rows, 256-bit aligned)

struct SmemGemm {
    __nv_bfloat16 Ah[128][SLD];
    __nv_bfloat16 Al[128][SLD];
    __nv_bfloat16 Bh[128][SLD];
    __nv_bfloat16 Bl[128][SLD];
};
// max(mainloop 81920 B, epilogue 128*136*4 = 69632 B)
#define SMEM_GEMM_BYTES ((int)sizeof(SmemGemm))

__global__ void __launch_bounds__(256, 1)
k_gemm_wmma(const float* __restrict__ bias, float* __restrict__ out)
{
    extern __shared__ __align__(32) char smraw[];
    SmemGemm* sm = reinterpret_cast<SmemGemm*>(smraw);
    float* tr = reinterpret_cast<float*>(smraw);   // reused for epilogue

    int tid = threadIdx.x;
    int wid = tid >> 5;
    int m0 = blockIdx.x * 128;
    int n0 = blockIdx.y * 128;
    int wm = wid >> 1;        // 0..3 -> 32-row slab
    int wn = wid & 1;         // 0..1 -> 64-col slab

    wmma::fragment<wmma::accumulator, 16, 16, 16, float> acc[2][4];
    #pragma unroll
    for (int i = 0; i < 2; ++i)
        #pragma unroll
        for (int j = 0; j < 4; ++j) wmma::fill_fragment(acc[i][j], 0.f);

    int lrow = tid >> 1;               // 0..127
    int lcol = (tid & 1) * 32;         // 0 or 32

    for (int ch = 0; ch < 4; ++ch) {
        int k0 = ch * 64;
        // load A hi/lo: row lrow, 32 bf16 starting at k0+lcol
        {
            const uint4* ga = reinterpret_cast<const uint4*>(
                g_Ah + (size_t)(m0 + lrow) * D_ + k0 + lcol);
            const uint4* gl = reinterpret_cast<const uint4*>(
                g_Al + (size_t)(m0 + lrow) * D_ + k0 + lcol);
            uint4* sa = reinterpret_cast<uint4*>(&sm->Ah[lrow][lcol]);
            uint4* sl = reinterpret_cast<uint4*>(&sm->Al[lrow][lcol]);
            #pragma unroll
            for (int u = 0; u < 4; ++u) { sa[u] = ga[u]; sl[u] = gl[u]; }
        }
        // load B hi/lo
        {
            const uint4* gb = reinterpret_cast<const uint4*>(
                g_Wh + (size_t)(n0 + lrow) * D_ + k0 + lcol);
            const uint4* gl = reinterpret_cast<const uint4*>(
                g_Wl + (size_t)(n0 + lrow) * D_ + k0 + lcol);
            uint4* sb = reinterpret_cast<uint4*>(&sm->Bh[lrow][lcol]);
            uint4* sl = reinterpret_cast<uint4*>(&sm->Bl[lrow][lcol]);
            #pragma unroll
            for (int u = 0; u < 4; ++u) { sb[u] = gb[u]; sl[u] = gl[u]; }
        }
        __syncthreads();

        #pragma unroll
        for (int kk = 0; kk < 4; ++kk) {
            int k = kk * 16;
            wmma::fragment<wmma::matrix_a, 16, 16, 16, __nv_bfloat16, wmma::row_major> fah[2], fal[2];
            wmma::fragment<wmma::matrix_b, 16, 16, 16, __nv_bfloat16, wmma::col_major> fbh[4], fbl[4];
            #pragma unroll
            for (int i = 0; i < 2; ++i) {
                wmma::load_matrix_sync(fah[i], &sm->Ah[wm * 32 + i * 16][k], SLD);
                wmma::load_matrix_sync(fal[i], &sm->Al[wm * 32 + i * 16][k], SLD);
            }
            #pragma unroll
            for (int j = 0; j < 4; ++j) {
                wmma::load_matrix_sync(fbh[j], &sm->Bh[wn * 64 + j * 16][k], SLD);
                wmma::load_matrix_sync(fbl[j], &sm->Bl[wn * 64 + j * 16][k], SLD);
            }
            #pragma unroll
            for (int i = 0; i < 2; ++i)
                #pragma unroll
                for (int j = 0; j < 4; ++j) {
                    wmma::mma_sync(acc[i][j], fah[i], fbh[j], acc[i][j]);
                    wmma::mma_sync(acc[i][j], fah[i], fbl[j], acc[i][j]);
                    wmma::mma_sync(acc[i][j], fal[i], fbh[j], acc[i][j]);
                }
        }
        __syncthreads();
    }

    // epilogue: fragments -> smem -> coalesced global with bias
    #pragma unroll
    for (int i = 0; i < 2; ++i)
        #pragma unroll
        for (int j = 0; j < 4; ++j)
            wmma::store_matrix_sync(tr + (size_t)(wm * 32 + i * 16) * TLD + wn * 64 + j * 16,
                                    acc[i][j], TLD, wmma::mem_row_major);
    __syncthreads();

    #pragma unroll 4
    for (int idx = tid; idx < 128 * 128; idx += 256) {
        int row = idx >> 7, col = idx & 127;
        int g = n0 + col;
        if (g < C_)
            out[(size_t)(m0 + row) * C_ + g] = tr[row * TLD + col] + __ldg(&bias[g]);
    }
}

// ---------------------------------------------------------------------------
// launcher
// ---------------------------------------------------------------------------
extern "C" void kernel_launch(void* const* d_in, const int* in_sizes, int n_in,
                              void* d_out, int out_size)
{
    const int*   leaf  = (const int*)  d_in[1];
    const int*   cmask = (const int*)  d_in[2];
    const int*   cinfo = (const int*)  d_in[3];
    const float* emb   = (const float*)d_in[4];
    const float* W     = (const float*)d_in[5];
    const float* bias  = (const float*)d_in[6];
    float* out = (float*)d_out;

    int n4 = (B_ * N_ * D_) / 4;
    k_zero<<<8192, 256>>>(n4);
    k_scatter_norm<<<B_ * L_, D_ / 4>>>(leaf, cmask, emb);
    k_convW<<<512, 64>>>(W);
    k_compose<<<B_, 256>>>(cinfo);
    k_convA<<<8192, 256>>>(n4);

    cudaFuncSetAttribute(k_gemm_wmma, cudaFuncAttributeMaxDynamicSharedMemorySize,
                         SMEM_GEMM_BYTES);
    dim3 ggrid(1023, 4);
    k_gemm_wmma<<<ggrid, 256, SMEM_GEMM_BYTES>>>(bias, out);
}

// round 10
// speedup vs baseline: 1.3984x; 1.1206x over previous
#include <cuda_runtime.h>
#include <cuda_bf16.h>
#include <mma.h>
#include <math.h>
#include <stdint.h>

using namespace nvcuda;

#define B_  128
#define L_  512
#define N_  1023
#define T_  511
#define D_  256
#define V_  50000
#define C_  511
#define EPSF 1e-6f

#define M_TOT (B_ * N_)          // 130944

// Scratch
__device__ float g_v[(size_t)B_ * N_ * D_];                        // 134 MB
__device__ __align__(16) __nv_bfloat16 g_Ah[(size_t)M_TOT * D_];   // 67 MB
__device__ __align__(16) __nv_bfloat16 g_Al[(size_t)M_TOT * D_];   // 67 MB
__device__ __align__(16) __nv_bfloat16 g_Wh[512 * 256];            // W hi (row 511 zero)
__device__ __align__(16) __nv_bfloat16 g_Wl[512 * 256];            // W lo

// ---------------------------------------------------------------------------
// cp.async helpers (Ampere+ baseline, valid on plain sm_103)
// ---------------------------------------------------------------------------
__device__ __forceinline__ void cp16(void* smem_dst, const void* gmem_src) {
    uint32_t s = (uint32_t)__cvta_generic_to_shared(smem_dst);
    asm volatile("cp.async.cg.shared.global [%0], [%1], 16;\n" :: "r"(s), "l"(gmem_src));
}
#define CP_COMMIT() asm volatile("cp.async.commit_group;\n" ::: "memory")
#define CP_WAIT1()  asm volatile("cp.async.wait_group 1;\n" ::: "memory")
#define CP_WAIT0()  asm volatile("cp.async.wait_group 0;\n" ::: "memory")

// ---------------------------------------------------------------------------
// Stage 0: zero node buffer
// ---------------------------------------------------------------------------
__global__ void k_zero(int n4) {
    float4* p = reinterpret_cast<float4*>(g_v);
    int i = blockIdx.x * blockDim.x + threadIdx.x;
    int stride = gridDim.x * blockDim.x;
    float4 z = make_float4(0.f, 0.f, 0.f, 0.f);
    for (; i < n4; i += stride) p[i] = z;
}

// ---------------------------------------------------------------------------
// Stage 1: scatter leaf embeddings, L2-normalized, into g_v (fused)
// ---------------------------------------------------------------------------
__global__ void k_scatter_norm(const int* __restrict__ leaf,
                               const int* __restrict__ cmask,
                               const float* __restrict__ emb) {
    int bl = blockIdx.x;
    if (cmask[bl] == 0) return;
    int idx = leaf[2 * bl + 0];
    int vid = leaf[2 * bl + 1];
    if ((unsigned)idx >= (unsigned)N_) return;
    int b = bl / L_;
    const float4* src = reinterpret_cast<const float4*>(emb + (size_t)vid * D_);
    float4 x = src[threadIdx.x];
    float s = x.x * x.x + x.y * x.y + x.z * x.z + x.w * x.w;
    #pragma unroll
    for (int o = 16; o; o >>= 1) s += __shfl_xor_sync(0xffffffffu, s, o);
    __shared__ float sh[2];
    if ((threadIdx.x & 31) == 0) sh[threadIdx.x >> 5] = s;
    __syncthreads();
    float sc = 1.f / (sqrtf(sh[0] + sh[1]) + EPSF);
    x.x *= sc; x.y *= sc; x.z *= sc; x.w *= sc;
    float4* dst = reinterpret_cast<float4*>(g_v + ((size_t)b * N_ + idx) * D_);
    dst[threadIdx.x] = x;
}

// ---------------------------------------------------------------------------
// Stage 1b: convert W to bf16 hi/lo (512 rows, row 511 zero)
// ---------------------------------------------------------------------------
__global__ void k_convW(const float* __restrict__ W) {
    int row = blockIdx.x;
    int c = threadIdx.x * 4;
    __nv_bfloat16 h[4], l[4];
    if (row < C_) {
        float4 w = *reinterpret_cast<const float4*>(W + (size_t)row * D_ + c);
        float f[4] = {w.x, w.y, w.z, w.w};
        #pragma unroll
        for (int i = 0; i < 4; ++i) {
            h[i] = __float2bfloat16(f[i]);
            l[i] = __float2bfloat16(f[i] - __bfloat162float(h[i]));
        }
    } else {
        #pragma unroll
        for (int i = 0; i < 4; ++i) { h[i] = __float2bfloat16(0.f); l[i] = h[i]; }
    }
    #pragma unroll
    for (int i = 0; i < 4; ++i) {
        g_Wh[(size_t)row * D_ + c + i] = h[i];
        g_Wl[(size_t)row * D_ + c + i] = l[i];
    }
}

// ---------------------------------------------------------------------------
// Stage 2: sequential tree composition, latency-pipelined.
// 1 block/batch, 256 threads. cinfo cached in SMEM; operands for step t+1
// prefetched during step t; index-hazard (l/r == p_t) reloaded at t+1.
// ---------------------------------------------------------------------------
__global__ void __launch_bounds__(256) k_compose(const int* __restrict__ cinfo)
{
    int b = blockIdx.x;
    float* v = g_v + (size_t)b * N_ * D_;
    const int4* info = reinterpret_cast<const int4*>(cinfo + (size_t)b * T_ * 4);

    __shared__ int4 sinfo[T_ + 1];
    __shared__ __align__(16) float sa[D_];
    __shared__ __align__(16) float sb[2 * D_];
    __shared__ float2 pp[128];
    __shared__ float sred[8];

    int tid = threadIdx.x;
    int lid = tid & 31;
    int wid = tid >> 5;
    int kk = (tid & 127) * 2;     // output pair
    int j0 = (tid >> 7) * 128;    // j half

    for (int i = tid; i < T_; i += 256) sinfo[i] = __ldg(&info[i]);
    if (tid == 0) sinfo[T_] = make_int4(0, 0, 0, 0);
    __syncthreads();

    // prefetch step-0 operands
    int4 ci = sinfo[0];
    float av = 0.f, bv = 0.f;
    if (ci.x) {
        av = v[(size_t)ci.z * D_ + tid];
        if (ci.x == 2) bv = v[(size_t)ci.w * D_ + tid];
    }
    int p_prev = -1;

    for (int t = 0; t < T_; ++t) {
        int4 nx = sinfo[t + 1];
        int ty = ci.x, p = ci.y, l = ci.z, r = ci.w;

        // hazard repair: prefetched operand was (possibly) stale vs prior write
        if (ty && p_prev >= 0) {
            if (l == p_prev) av = v[(size_t)l * D_ + tid];
            if (ty == 2 && r == p_prev) bv = v[(size_t)r * D_ + tid];
        }

        if (ty == 1) {
            float avc = av;
            // prefetch next (racy vs own store below; repaired at t+1)
            if (nx.x) {
                av = v[(size_t)nx.z * D_ + tid];
                if (nx.x == 2) bv = v[(size_t)nx.w * D_ + tid];
            }
            v[(size_t)p * D_ + tid] = avc;
            __syncthreads();
            p_prev = p;
        } else if (ty == 2) {
            sa[tid] = av;
            sb[tid] = bv;
            sb[tid + 256] = bv;
            __syncthreads();

            // prefetch next step's operands; overlaps the inner loop
            float avn = 0.f, bvn = 0.f;
            if (nx.x) {
                avn = v[(size_t)nx.z * D_ + tid];
                if (nx.x == 2) bvn = v[(size_t)nx.w * D_ + tid];
            }

            float2 w = *reinterpret_cast<const float2*>(sb + j0 + kk);
            float c0a = 0.f, c0b = 0.f, c1a = 0.f, c1b = 0.f;
            #pragma unroll
            for (int j = j0; j < j0 + 128; j += 4) {
                float4 aj = *reinterpret_cast<const float4*>(sa + j);
                float2 n1 = *reinterpret_cast<const float2*>(sb + j + 2 + kk);
                float2 n2 = *reinterpret_cast<const float2*>(sb + j + 4 + kk);
                c0a = fmaf(aj.x, w.x,  c0a);
                c0a = fmaf(aj.y, w.y,  c0a);
                c0b = fmaf(aj.z, n1.x, c0b);
                c0b = fmaf(aj.w, n1.y, c0b);
                c1a = fmaf(aj.x, w.y,  c1a);
                c1a = fmaf(aj.y, n1.x, c1a);
                c1b = fmaf(aj.z, n1.y, c1b);
                c1b = fmaf(aj.w, n2.x, c1b);
                w = n2;
            }
            float c0 = c0a + c0b;
            float c1 = c1a + c1b;

            if (tid >= 128) pp[tid & 127] = make_float2(c0, c1);
            __syncthreads();

            float s = 0.f;
            if (tid < 128) {
                float2 q = pp[tid];
                c0 += q.x; c1 += q.y;
                s = c0 * c0 + c1 * c1;
            }
            #pragma unroll
            for (int o = 16; o; o >>= 1) s += __shfl_xor_sync(0xffffffffu, s, o);
            if (lid == 0) sred[wid] = s;
            __syncthreads();
            float tot = sred[0] + sred[1] + sred[2] + sred[3];
            if (tid < 128) {
                float sc = 1.f / (sqrtf(tot) + EPSF);
                *reinterpret_cast<float2*>(v + (size_t)p * D_ + kk) =
                    make_float2(c0 * sc, c1 * sc);
            }
            __syncthreads();
            av = avn; bv = bvn;
            p_prev = p;
        } else {
            // ty == 0: no write; just prefetch next
            if (nx.x) {
                av = v[(size_t)nx.z * D_ + tid];
                if (nx.x == 2) bv = v[(size_t)nx.w * D_ + tid];
            }
            p_prev = -1;
        }
        ci = nx;
    }
}

// ---------------------------------------------------------------------------
// Stage 2b: convert composed node vectors fp32 -> bf16 hi/lo
// ---------------------------------------------------------------------------
__global__ void k_convA(int n4) {
    const float4* src = reinterpret_cast<const float4*>(g_v);
    uint2* ah = reinterpret_cast<uint2*>(g_Ah);
    uint2* al = reinterpret_cast<uint2*>(g_Al);
    int i = blockIdx.x * blockDim.x + threadIdx.x;
    int stride = gridDim.x * blockDim.x;
    for (; i < n4; i += stride) {
        float4 x = src[i];
        __nv_bfloat16 h0 = __float2bfloat16(x.x), h1 = __float2bfloat16(x.y);
        __nv_bfloat16 h2 = __float2bfloat16(x.z), h3 = __float2bfloat16(x.w);
        __nv_bfloat16 l0 = __float2bfloat16(x.x - __bfloat162float(h0));
        __nv_bfloat16 l1 = __float2bfloat16(x.y - __bfloat162float(h1));
        __nv_bfloat16 l2 = __float2bfloat16(x.z - __bfloat162float(h2));
        __nv_bfloat16 l3 = __float2bfloat16(x.w - __bfloat162float(h3));
        __nv_bfloat162 hA = {h0, h1}, hB = {h2, h3}, lA = {l0, l1}, lB = {l2, l3};
        ah[i] = make_uint2(*reinterpret_cast<uint32_t*>(&hA),
                           *reinterpret_cast<uint32_t*>(&hB));
        al[i] = make_uint2(*reinterpret_cast<uint32_t*>(&lA),
                           *reinterpret_cast<uint32_t*>(&lB));
    }
}

// ---------------------------------------------------------------------------
// Stage 3: WMMA bf16-split GEMM with cp.async double buffering.
// out[m, n] = sum_k v[m,k] * W[n,k] + bias[n]
// Grid (1023, 4): CTA = 128 M x 128 N.  8 warps, warp = 32 M x 64 N.
// K chunked by 64.  acc += Ah*Bh + Ah*Bl + Al*Bh.
// ---------------------------------------------------------------------------
#define SLD 80      // bf16 smem leading dim (160 B rows, 256-bit aligned)
#define TLD 136     // f32 epilogue leading dim (544 B rows, 256-bit aligned)

struct SmemGemm {
    __nv_bfloat16 Ah[128][SLD];
    __nv_bfloat16 Al[128][SLD];
    __nv_bfloat16 Bh[128][SLD];
    __nv_bfloat16 Bl[128][SLD];
};
#define SMEM_GEMM_BYTES (2 * (int)sizeof(SmemGemm))   // 163840 B

__device__ __forceinline__ void gemm_load_chunk(SmemGemm* sm, int m0, int n0,
                                                int ch, int lrow, int lcol) {
    int k0 = ch * 64;
    const __nv_bfloat16* ga = g_Ah + (size_t)(m0 + lrow) * D_ + k0 + lcol;
    const __nv_bfloat16* gA = g_Al + (size_t)(m0 + lrow) * D_ + k0 + lcol;
    const __nv_bfloat16* gb = g_Wh + (size_t)(n0 + lrow) * D_ + k0 + lcol;
    const __nv_bfloat16* gB = g_Wl + (size_t)(n0 + lrow) * D_ + k0 + lcol;
    #pragma unroll
    for (int u = 0; u < 4; ++u) {
        cp16(&sm->Ah[lrow][lcol + u * 8], ga + u * 8);
        cp16(&sm->Al[lrow][lcol + u * 8], gA + u * 8);
        cp16(&sm->Bh[lrow][lcol + u * 8], gb + u * 8);
        cp16(&sm->Bl[lrow][lcol + u * 8], gB + u * 8);
    }
}

__global__ void __launch_bounds__(256, 1)
k_gemm_wmma(const float* __restrict__ bias, float* __restrict__ out)
{
    extern __shared__ __align__(32) char smraw[];
    SmemGemm* buf0 = reinterpret_cast<SmemGemm*>(smraw);
    SmemGemm* buf1 = reinterpret_cast<SmemGemm*>(smraw + sizeof(SmemGemm));
    float* tr = reinterpret_cast<float*>(smraw);   // reused for epilogue

    int tid = threadIdx.x;
    int wid = tid >> 5;
    int m0 = blockIdx.x * 128;
    int n0 = blockIdx.y * 128;
    int wm = wid >> 1;        // 0..3 -> 32-row slab
    int wn = wid & 1;         // 0..1 -> 64-col slab

    wmma::fragment<wmma::accumulator, 16, 16, 16, float> acc[2][4];
    #pragma unroll
    for (int i = 0; i < 2; ++i)
        #pragma unroll
        for (int j = 0; j < 4; ++j) wmma::fill_fragment(acc[i][j], 0.f);

    int lrow = tid >> 1;               // 0..127
    int lcol = (tid & 1) * 32;         // 0 or 32

    gemm_load_chunk(buf0, m0, n0, 0, lrow, lcol);
    CP_COMMIT();

    for (int ch = 0; ch < 4; ++ch) {
        SmemGemm* cur = (ch & 1) ? buf1 : buf0;
        if (ch < 3) {
            SmemGemm* nxt = (ch & 1) ? buf0 : buf1;
            gemm_load_chunk(nxt, m0, n0, ch + 1, lrow, lcol);
            CP_COMMIT();
            CP_WAIT1();
        } else {
            CP_WAIT0();
        }
        __syncthreads();

        #pragma unroll
        for (int kk = 0; kk < 4; ++kk) {
            int k = kk * 16;
            wmma::fragment<wmma::matrix_a, 16, 16, 16, __nv_bfloat16, wmma::row_major> fah[2], fal[2];
            wmma::fragment<wmma::matrix_b, 16, 16, 16, __nv_bfloat16, wmma::col_major> fbh[4], fbl[4];
            #pragma unroll
            for (int i = 0; i < 2; ++i) {
                wmma::load_matrix_sync(fah[i], &cur->Ah[wm * 32 + i * 16][k], SLD);
                wmma::load_matrix_sync(fal[i], &cur->Al[wm * 32 + i * 16][k], SLD);
            }
            #pragma unroll
            for (int j = 0; j < 4; ++j) {
                wmma::load_matrix_sync(fbh[j], &cur->Bh[wn * 64 + j * 16][k], SLD);
                wmma::load_matrix_sync(fbl[j], &cur->Bl[wn * 64 + j * 16][k], SLD);
            }
            #pragma unroll
            for (int i = 0; i < 2; ++i)
                #pragma unroll
                for (int j = 0; j < 4; ++j) {
                    wmma::mma_sync(acc[i][j], fah[i], fbh[j], acc[i][j]);
                    wmma::mma_sync(acc[i][j], fah[i], fbl[j], acc[i][j]);
                    wmma::mma_sync(acc[i][j], fal[i], fbh[j], acc[i][j]);
                }
        }
        __syncthreads();
    }

    // epilogue: fragments -> smem -> coalesced global with bias
    #pragma unroll
    for (int i = 0; i < 2; ++i)
        #pragma unroll
        for (int j = 0; j < 4; ++j)
            wmma::store_matrix_sync(tr + (size_t)(wm * 32 + i * 16) * TLD + wn * 64 + j * 16,
                                    acc[i][j], TLD, wmma::mem_row_major);
    __syncthreads();

    #pragma unroll 4
    for (int idx = tid; idx < 128 * 128; idx += 256) {
        int row = idx >> 7, col = idx & 127;
        int g = n0 + col;
        if (g < C_)
            out[(size_t)(m0 + row) * C_ + g] = tr[row * TLD + col] + __ldg(&bias[g]);
    }
}

// ---------------------------------------------------------------------------
// launcher
// ---------------------------------------------------------------------------
extern "C" void kernel_launch(void* const* d_in, const int* in_sizes, int n_in,
                              void* d_out, int out_size)
{
    const int*   leaf  = (const int*)  d_in[1];
    const int*   cmask = (const int*)  d_in[2];
    const int*   cinfo = (const int*)  d_in[3];
    const float* emb   = (const float*)d_in[4];
    const float* W     = (const float*)d_in[5];
    const float* bias  = (const float*)d_in[6];
    float* out = (float*)d_out;

    int n4 = (B_ * N_ * D_) / 4;
    k_zero<<<8192, 256>>>(n4);
    k_scatter_norm<<<B_ * L_, D_ / 4>>>(leaf, cmask, emb);
    k_convW<<<512, 64>>>(W);
    k_compose<<<B_, 256>>>(cinfo);
    k_convA<<<8192, 256>>>(n4);

    cudaFuncSetAttribute(k_gemm_wmma, cudaFuncAttributeMaxDynamicSharedMemorySize,
                         SMEM_GEMM_BYTES);
    dim3 ggrid(1023, 4);
    k_gemm_wmma<<<ggrid, 256, SMEM_GEMM_BYTES>>>(bias, out);
}

// round 13
// speedup vs baseline: 1.4464x; 1.0343x over previous
#include <cuda_runtime.h>
#include <cuda_bf16.h>
#include <mma.h>
#include <math.h>
#include <stdint.h>

using namespace nvcuda;

#define B_  128
#define L_  512
#define N_  1023
#define T_  511
#define D_  256
#define V_  50000
#define C_  511
#define EPSF 1e-6f

#define M_TOT (B_ * N_)          // 130944

// Scratch
__device__ float g_v[(size_t)B_ * N_ * D_];                        // 134 MB
__device__ __align__(16) __nv_bfloat16 g_Ah[(size_t)M_TOT * D_];   // 67 MB
__device__ __align__(16) __nv_bfloat16 g_Al[(size_t)M_TOT * D_];   // 67 MB
__device__ __align__(16) __nv_bfloat16 g_Wh[512 * 256];            // W hi (row 511 zero)
__device__ __align__(16) __nv_bfloat16 g_Wl[512 * 256];            // W lo

// ---------------------------------------------------------------------------
// cp.async helpers
// ---------------------------------------------------------------------------
__device__ __forceinline__ void cp16(void* smem_dst, const void* gmem_src) {
    uint32_t s = (uint32_t)__cvta_generic_to_shared(smem_dst);
    asm volatile("cp.async.cg.shared.global [%0], [%1], 16;\n" :: "r"(s), "l"(gmem_src));
}
#define CP_COMMIT() asm volatile("cp.async.commit_group;\n" ::: "memory")
#define CP_WAIT1()  asm volatile("cp.async.wait_group 1;\n" ::: "memory")
#define CP_WAIT0()  asm volatile("cp.async.wait_group 0;\n" ::: "memory")

// ---------------------------------------------------------------------------
// Stage 0: zero node buffer
// ---------------------------------------------------------------------------
__global__ void k_zero(int n4) {
    float4* p = reinterpret_cast<float4*>(g_v);
    int i = blockIdx.x * blockDim.x + threadIdx.x;
    int stride = gridDim.x * blockDim.x;
    float4 z = make_float4(0.f, 0.f, 0.f, 0.f);
    for (; i < n4; i += stride) p[i] = z;
}

// ---------------------------------------------------------------------------
// Stage 1: scatter leaf embeddings, L2-normalized, into g_v (fused)
// ---------------------------------------------------------------------------
__global__ void k_scatter_norm(const int* __restrict__ leaf,
                               const int* __restrict__ cmask,
                               const float* __restrict__ emb) {
    int bl = blockIdx.x;
    if (cmask[bl] == 0) return;
    int idx = leaf[2 * bl + 0];
    int vid = leaf[2 * bl + 1];
    if ((unsigned)idx >= (unsigned)N_) return;
    int b = bl / L_;
    const float4* src = reinterpret_cast<const float4*>(emb + (size_t)vid * D_);
    float4 x = src[threadIdx.x];
    float s = x.x * x.x + x.y * x.y + x.z * x.z + x.w * x.w;
    #pragma unroll
    for (int o = 16; o; o >>= 1) s += __shfl_xor_sync(0xffffffffu, s, o);
    __shared__ float sh[2];
    if ((threadIdx.x & 31) == 0) sh[threadIdx.x >> 5] = s;
    __syncthreads();
    float sc = 1.f / (sqrtf(sh[0] + sh[1]) + EPSF);
    x.x *= sc; x.y *= sc; x.z *= sc; x.w *= sc;
    float4* dst = reinterpret_cast<float4*>(g_v + ((size_t)b * N_ + idx) * D_);
    dst[threadIdx.x] = x;
}

// ---------------------------------------------------------------------------
// Stage 1b: convert W to bf16 hi/lo (512 rows, row 511 zero)
// ---------------------------------------------------------------------------
__global__ void k_convW(const float* __restrict__ W) {
    int row = blockIdx.x;
    int c = threadIdx.x * 4;
    __nv_bfloat16 h[4], l[4];
    if (row < C_) {
        float4 w = *reinterpret_cast<const float4*>(W + (size_t)row * D_ + c);
        float f[4] = {w.x, w.y, w.z, w.w};
        #pragma unroll
        for (int i = 0; i < 4; ++i) {
            h[i] = __float2bfloat16(f[i]);
            l[i] = __float2bfloat16(f[i] - __bfloat162float(h[i]));
        }
    } else {
        #pragma unroll
        for (int i = 0; i < 4; ++i) { h[i] = __float2bfloat16(0.f); l[i] = h[i]; }
    }
    #pragma unroll
    for (int i = 0; i < 4; ++i) {
        g_Wh[(size_t)row * D_ + c + i] = h[i];
        g_Wl[(size_t)row * D_ + c + i] = l[i];
    }
}

// ---------------------------------------------------------------------------
// Stage 2: sequential tree composition. 1 block/batch, 512 threads (16 warps).
// Thread layout: output group og = (tid&63)*4 (4 outputs), j-chunk jc = tid>>6
// (32 j's). Each 16B b-window load feeds 16 MACs (halves LDS traffic).
// cinfo in SMEM; operands prefetched one step ahead with hazard repair.
// ---------------------------------------------------------------------------
__global__ void __launch_bounds__(512) k_compose(const int* __restrict__ cinfo)
{
    int b = blockIdx.x;
    float* v = g_v + (size_t)b * N_ * D_;
    const int4* info = reinterpret_cast<const int4*>(cinfo + (size_t)b * T_ * 4);

    __shared__ int4 sinfo[T_ + 1];
    __shared__ __align__(16) float sa[D_];
    __shared__ __align__(16) float sb[2 * D_];
    __shared__ __align__(16) float pp2[8][260];
    __shared__ float sred[8];

    int tid = threadIdx.x;
    int lid = tid & 31;
    int wid = tid >> 5;
    int og = (tid & 63) * 4;      // output group base: 0..252
    int jb = (tid >> 6) * 32;     // j chunk base: 0..224
    int jc = tid >> 6;

    for (int i = tid; i < T_; i += 512) sinfo[i] = __ldg(&info[i]);
    if (tid == 0) sinfo[T_] = make_int4(0, 0, 0, 0);
    __syncthreads();

    // prefetch step-0 operands (tid<256 holds one lane of each vector)
    int4 ci = sinfo[0];
    float av = 0.f, bv = 0.f;
    if (tid < 256 && ci.x) {
        av = v[(size_t)ci.z * D_ + tid];
        if (ci.x == 2) bv = v[(size_t)ci.w * D_ + tid];
    }
    int p_prev = -1;

    for (int t = 0; t < T_; ++t) {
        int4 nx = sinfo[t + 1];
        int ty = ci.x, p = ci.y, l = ci.z, r = ci.w;

        // hazard repair: only step t-1's write can be invisible to the prefetch
        if (tid < 256 && ty && p_prev >= 0) {
            if (l == p_prev) av = v[(size_t)l * D_ + tid];
            if (ty == 2 && r == p_prev) bv = v[(size_t)r * D_ + tid];
        }

        if (ty == 1) {
            float avc = av;
            if (tid < 256 && nx.x) {
                av = v[(size_t)nx.z * D_ + tid];
                if (nx.x == 2) bv = v[(size_t)nx.w * D_ + tid];
            }
            if (tid < 256) v[(size_t)p * D_ + tid] = avc;
            __syncthreads();
            p_prev = p;
        } else if (ty == 2) {
            if (tid < 256) {
                sa[tid] = av;
                sb[tid] = bv;
                sb[tid + 256] = bv;
            }
            __syncthreads();

            // prefetch next step's operands (overlaps inner loop)
            float avn = 0.f, bvn = 0.f;
            if (tid < 256 && nx.x) {
                avn = v[(size_t)nx.z * D_ + tid];
                if (nx.x == 2) bvn = v[(size_t)nx.w * D_ + tid];
            }

            // c[og+d] partial over j in [jb, jb+32):  c_d += a[j] * b[j+og+d]
            float4 w = *reinterpret_cast<const float4*>(sb + jb + og);
            float c0 = 0.f, c1 = 0.f, c2 = 0.f, c3 = 0.f;
            #pragma unroll
            for (int j = 0; j < 32; j += 4) {
                float4 a4 = *reinterpret_cast<const float4*>(sa + jb + j);
                float4 n4 = *reinterpret_cast<const float4*>(sb + jb + j + og + 4);
                c0 = fmaf(a4.x, w.x,  c0); c1 = fmaf(a4.x, w.y,  c1);
                c2 = fmaf(a4.x, w.z,  c2); c3 = fmaf(a4.x, w.w,  c3);
                c0 = fmaf(a4.y, w.y,  c0); c1 = fmaf(a4.y, w.z,  c1);
                c2 = fmaf(a4.y, w.w,  c2); c3 = fmaf(a4.y, n4.x, c3);
                c0 = fmaf(a4.z, w.z,  c0); c1 = fmaf(a4.z, w.w,  c1);
                c2 = fmaf(a4.z, n4.x, c2); c3 = fmaf(a4.z, n4.y, c3);
                c0 = fmaf(a4.w, w.w,  c0); c1 = fmaf(a4.w, n4.x, c1);
                c2 = fmaf(a4.w, n4.y, c2); c3 = fmaf(a4.w, n4.z, c3);
                w = n4;
            }
            *reinterpret_cast<float4*>(&pp2[jc][og]) = make_float4(c0, c1, c2, c3);
            __syncthreads();

            float s = 0.f, c = 0.f;
            if (tid < 256) {
                c = pp2[0][tid] + pp2[1][tid] + pp2[2][tid] + pp2[3][tid]
                  + pp2[4][tid] + pp2[5][tid] + pp2[6][tid] + pp2[7][tid];
                s = c * c;
            }
            #pragma unroll
            for (int o = 16; o; o >>= 1) s += __shfl_xor_sync(0xffffffffu, s, o);
            if (lid == 0 && wid < 8) sred[wid] = s;
            __syncthreads();
            float tot = sred[0] + sred[1] + sred[2] + sred[3]
                      + sred[4] + sred[5] + sred[6] + sred[7];
            if (tid < 256) {
                float sc = 1.f / (sqrtf(tot) + EPSF);
                v[(size_t)p * D_ + tid] = c * sc;
            }
            __syncthreads();
            av = avn; bv = bvn;
            p_prev = p;
        } else {
            // ty == 0: no write, no shared-state touch; just prefetch
            if (tid < 256 && nx.x) {
                av = v[(size_t)nx.z * D_ + tid];
                if (nx.x == 2) bv = v[(size_t)nx.w * D_ + tid];
            }
            p_prev = -1;
        }
        ci = nx;
    }
}

// ---------------------------------------------------------------------------
// Stage 2b: convert composed node vectors fp32 -> bf16 hi/lo
// ---------------------------------------------------------------------------
__global__ void k_convA(int n4) {
    const float4* src = reinterpret_cast<const float4*>(g_v);
    uint2* ah = reinterpret_cast<uint2*>(g_Ah);
    uint2* al = reinterpret_cast<uint2*>(g_Al);
    int i = blockIdx.x * blockDim.x + threadIdx.x;
    int stride = gridDim.x * blockDim.x;
    for (; i < n4; i += stride) {
        float4 x = src[i];
        __nv_bfloat16 h0 = __float2bfloat16(x.x), h1 = __float2bfloat16(x.y);
        __nv_bfloat16 h2 = __float2bfloat16(x.z), h3 = __float2bfloat16(x.w);
        __nv_bfloat16 l0 = __float2bfloat16(x.x - __bfloat162float(h0));
        __nv_bfloat16 l1 = __float2bfloat16(x.y - __bfloat162float(h1));
        __nv_bfloat16 l2 = __float2bfloat16(x.z - __bfloat162float(h2));
        __nv_bfloat16 l3 = __float2bfloat16(x.w - __bfloat162float(h3));
        __nv_bfloat162 hA = {h0, h1}, hB = {h2, h3}, lA = {l0, l1}, lB = {l2, l3};
        ah[i] = make_uint2(*reinterpret_cast<uint32_t*>(&hA),
                           *reinterpret_cast<uint32_t*>(&hB));
        al[i] = make_uint2(*reinterpret_cast<uint32_t*>(&lA),
                           *reinterpret_cast<uint32_t*>(&lB));
    }
}

// ---------------------------------------------------------------------------
// Stage 3: WMMA bf16-split GEMM, cp.async double buffering, TERM-MAJOR mma
// ordering (dependency distance 8 on each accumulator instead of 1).
// ---------------------------------------------------------------------------
#define SLD 80      // bf16 smem leading dim (160 B rows, 256-bit aligned)
#define TLD 136     // f32 epilogue leading dim (544 B rows, 256-bit aligned)

struct SmemGemm {
    __nv_bfloat16 Ah[128][SLD];
    __nv_bfloat16 Al[128][SLD];
    __nv_bfloat16 Bh[128][SLD];
    __nv_bfloat16 Bl[128][SLD];
};
#define SMEM_GEMM_BYTES (2 * (int)sizeof(SmemGemm))   // 163840 B

__device__ __forceinline__ void gemm_load_chunk(SmemGemm* sm, int m0, int n0,
                                                int ch, int lrow, int lcol) {
    int k0 = ch * 64;
    const __nv_bfloat16* ga = g_Ah + (size_t)(m0 + lrow) * D_ + k0 + lcol;
    const __nv_bfloat16* gA = g_Al + (size_t)(m0 + lrow) * D_ + k0 + lcol;
    const __nv_bfloat16* gb = g_Wh + (size_t)(n0 + lrow) * D_ + k0 + lcol;
    const __nv_bfloat16* gB = g_Wl + (size_t)(n0 + lrow) * D_ + k0 + lcol;
    #pragma unroll
    for (int u = 0; u < 4; ++u) {
        cp16(&sm->Ah[lrow][lcol + u * 8], ga + u * 8);
        cp16(&sm->Al[lrow][lcol + u * 8], gA + u * 8);
        cp16(&sm->Bh[lrow][lcol + u * 8], gb + u * 8);
        cp16(&sm->Bl[lrow][lcol + u * 8], gB + u * 8);
    }
}

__global__ void __launch_bounds__(256, 1)
k_gemm_wmma(const float* __restrict__ bias, float* __restrict__ out)
{
    extern __shared__ __align__(32) char smraw[];
    SmemGemm* buf0 = reinterpret_cast<SmemGemm*>(smraw);
    SmemGemm* buf1 = reinterpret_cast<SmemGemm*>(smraw + sizeof(SmemGemm));
    float* tr = reinterpret_cast<float*>(smraw);   // reused for epilogue

    int tid = threadIdx.x;
    int wid = tid >> 5;
    int m0 = blockIdx.x * 128;
    int n0 = blockIdx.y * 128;
    int wm = wid >> 1;        // 0..3 -> 32-row slab
    int wn = wid & 1;         // 0..1 -> 64-col slab

    wmma::fragment<wmma::accumulator, 16, 16, 16, float> acc[2][4];
    #pragma unroll
    for (int i = 0; i < 2; ++i)
        #pragma unroll
        for (int j = 0; j < 4; ++j) wmma::fill_fragment(acc[i][j], 0.f);

    int lrow = tid >> 1;               // 0..127
    int lcol = (tid & 1) * 32;         // 0 or 32

    gemm_load_chunk(buf0, m0, n0, 0, lrow, lcol);
    CP_COMMIT();

    for (int ch = 0; ch < 4; ++ch) {
        SmemGemm* cur = (ch & 1) ? buf1 : buf0;
        if (ch < 3) {
            SmemGemm* nxt = (ch & 1) ? buf0 : buf1;
            gemm_load_chunk(nxt, m0, n0, ch + 1, lrow, lcol);
            CP_COMMIT();
            CP_WAIT1();
        } else {
            CP_WAIT0();
        }
        __syncthreads();

        #pragma unroll
        for (int kk = 0; kk < 4; ++kk) {
            int k = kk * 16;
            wmma::fragment<wmma::matrix_a, 16, 16, 16, __nv_bfloat16, wmma::row_major> fah[2], fal[2];
            wmma::fragment<wmma::matrix_b, 16, 16, 16, __nv_bfloat16, wmma::col_major> fbh[4], fbl[4];
            #pragma unroll
            for (int i = 0; i < 2; ++i) {
                wmma::load_matrix_sync(fah[i], &cur->Ah[wm * 32 + i * 16][k], SLD);
                wmma::load_matrix_sync(fal[i], &cur->Al[wm * 32 + i * 16][k], SLD);
            }
            #pragma unroll
            for (int j = 0; j < 4; ++j) {
                wmma::load_matrix_sync(fbh[j], &cur->Bh[wn * 64 + j * 16][k], SLD);
                wmma::load_matrix_sync(fbl[j], &cur->Bl[wn * 64 + j * 16][k], SLD);
            }
            // term-major: consecutive mmas always hit different accumulators
            #pragma unroll
            for (int i = 0; i < 2; ++i)
                #pragma unroll
                for (int j = 0; j < 4; ++j)
                    wmma::mma_sync(acc[i][j], fah[i], fbh[j], acc[i][j]);
            #pragma unroll
            for (int i = 0; i < 2; ++i)
                #pragma unroll
                for (int j = 0; j < 4; ++j)
                    wmma::mma_sync(acc[i][j], fah[i], fbl[j], acc[i][j]);
            #pragma unroll
            for (int i = 0; i < 2; ++i)
                #pragma unroll
                for (int j = 0; j < 4; ++j)
                    wmma::mma_sync(acc[i][j], fal[i], fbh[j], acc[i][j]);
        }
        __syncthreads();
    }

    // epilogue: fragments -> smem -> coalesced global with bias
    #pragma unroll
    for (int i = 0; i < 2; ++i)
        #pragma unroll
        for (int j = 0; j < 4; ++j)
            wmma::store_matrix_sync(tr + (size_t)(wm * 32 + i * 16) * TLD + wn * 64 + j * 16,
                                    acc[i][j], TLD, wmma::mem_row_major);
    __syncthreads();

    #pragma unroll 4
    for (int idx = tid; idx < 128 * 128; idx += 256) {
        int row = idx >> 7, col = idx & 127;
        int g = n0 + col;
        if (g < C_)
            out[(size_t)(m0 + row) * C_ + g] = tr[row * TLD + col] + __ldg(&bias[g]);
    }
}

// ---------------------------------------------------------------------------
// launcher
// ---------------------------------------------------------------------------
extern "C" void kernel_launch(void* const* d_in, const int* in_sizes, int n_in,
                              void* d_out, int out_size)
{
    const int*   leaf  = (const int*)  d_in[1];
    const int*   cmask = (const int*)  d_in[2];
    const int*   cinfo = (const int*)  d_in[3];
    const float* emb   = (const float*)d_in[4];
    const float* W     = (const float*)d_in[5];
    const float* bias  = (const float*)d_in[6];
    float* out = (float*)d_out;

    int n4 = (B_ * N_ * D_) / 4;
    k_zero<<<8192, 256>>>(n4);
    k_scatter_norm<<<B_ * L_, D_ / 4>>>(leaf, cmask, emb);
    k_convW<<<512, 64>>>(W);
    k_compose<<<B_, 512>>>(cinfo);
    k_convA<<<8192, 256>>>(n4);

    cudaFuncSetAttribute(k_gemm_wmma, cudaFuncAttributeMaxDynamicSharedMemorySize,
                         SMEM_GEMM_BYTES);
    dim3 ggrid(1023, 4);
    k_gemm_wmma<<<ggrid, 256, SMEM_GEMM_BYTES>>>(bias, out);
}

// round 14
// speedup vs baseline: 1.8476x; 1.2774x over previous
#include <cuda_runtime.h>
#include <cuda_fp16.h>
#include <mma.h>
#include <math.h>
#include <stdint.h>

using namespace nvcuda;

#define B_  128
#define L_  512
#define N_  1023
#define T_  511
#define D_  256
#define V_  50000
#define C_  511
#define EPSF 1e-6f

#define M_TOT (B_ * N_)          // 130944

// Scratch
__device__ float g_v[(size_t)B_ * N_ * D_];                 // 134 MB
__device__ __align__(16) __half g_Ah[(size_t)M_TOT * D_];   // 67 MB (fp16 hi)
__device__ __align__(16) __half g_Al[(size_t)M_TOT * D_];   // 67 MB (fp16 lo)
__device__ __align__(16) __half g_Wh[512 * 256];            // W fp16 (row 511 zero)

// ---------------------------------------------------------------------------
// cp.async helpers
// ---------------------------------------------------------------------------
__device__ __forceinline__ void cp16(void* smem_dst, const void* gmem_src) {
    uint32_t s = (uint32_t)__cvta_generic_to_shared(smem_dst);
    asm volatile("cp.async.cg.shared.global [%0], [%1], 16;\n" :: "r"(s), "l"(gmem_src));
}
#define CP_COMMIT() asm volatile("cp.async.commit_group;\n" ::: "memory")
#define CP_WAIT1()  asm volatile("cp.async.wait_group 1;\n" ::: "memory")
#define CP_WAIT0()  asm volatile("cp.async.wait_group 0;\n" ::: "memory")

// ---------------------------------------------------------------------------
// Stage 0: zero node buffer
// ---------------------------------------------------------------------------
__global__ void k_zero(int n4) {
    float4* p = reinterpret_cast<float4*>(g_v);
    int i = blockIdx.x * blockDim.x + threadIdx.x;
    int stride = gridDim.x * blockDim.x;
    float4 z = make_float4(0.f, 0.f, 0.f, 0.f);
    for (; i < n4; i += stride) p[i] = z;
}

// ---------------------------------------------------------------------------
// Stage 1: scatter leaf embeddings, L2-normalized, into g_v (fused)
// ---------------------------------------------------------------------------
__global__ void k_scatter_norm(const int* __restrict__ leaf,
                               const int* __restrict__ cmask,
                               const float* __restrict__ emb) {
    int bl = blockIdx.x;
    if (cmask[bl] == 0) return;
    int idx = leaf[2 * bl + 0];
    int vid = leaf[2 * bl + 1];
    if ((unsigned)idx >= (unsigned)N_) return;
    int b = bl / L_;
    const float4* src = reinterpret_cast<const float4*>(emb + (size_t)vid * D_);
    float4 x = src[threadIdx.x];
    float s = x.x * x.x + x.y * x.y + x.z * x.z + x.w * x.w;
    #pragma unroll
    for (int o = 16; o; o >>= 1) s += __shfl_xor_sync(0xffffffffu, s, o);
    __shared__ float sh[2];
    if ((threadIdx.x & 31) == 0) sh[threadIdx.x >> 5] = s;
    __syncthreads();
    float sc = 1.f / (sqrtf(sh[0] + sh[1]) + EPSF);
    x.x *= sc; x.y *= sc; x.z *= sc; x.w *= sc;
    float4* dst = reinterpret_cast<float4*>(g_v + ((size_t)b * N_ + idx) * D_);
    dst[threadIdx.x] = x;
}

// ---------------------------------------------------------------------------
// Stage 1b: convert W to fp16 (512 rows, row 511 zero)
// ---------------------------------------------------------------------------
__global__ void k_convW(const float* __restrict__ W) {
    int row = blockIdx.x;
    int c = threadIdx.x * 4;
    __half h[4];
    if (row < C_) {
        float4 w = *reinterpret_cast<const float4*>(W + (size_t)row * D_ + c);
        h[0] = __float2half_rn(w.x); h[1] = __float2half_rn(w.y);
        h[2] = __float2half_rn(w.z); h[3] = __float2half_rn(w.w);
    } else {
        #pragma unroll
        for (int i = 0; i < 4; ++i) h[i] = __float2half_rn(0.f);
    }
    #pragma unroll
    for (int i = 0; i < 4; ++i) g_Wh[(size_t)row * D_ + c + i] = h[i];
}

// ---------------------------------------------------------------------------
// Stage 2: sequential tree composition. 1 block/batch, 512 threads (16 warps).
// (unchanged from R13 — verified at 344 us, rel_err-neutral)
// ---------------------------------------------------------------------------
__global__ void __launch_bounds__(512) k_compose(const int* __restrict__ cinfo)
{
    int b = blockIdx.x;
    float* v = g_v + (size_t)b * N_ * D_;
    const int4* info = reinterpret_cast<const int4*>(cinfo + (size_t)b * T_ * 4);

    __shared__ int4 sinfo[T_ + 1];
    __shared__ __align__(16) float sa[D_];
    __shared__ __align__(16) float sb[2 * D_];
    __shared__ __align__(16) float pp2[8][260];
    __shared__ float sred[8];

    int tid = threadIdx.x;
    int lid = tid & 31;
    int wid = tid >> 5;
    int og = (tid & 63) * 4;      // output group base: 0..252
    int jb = (tid >> 6) * 32;     // j chunk base: 0..224
    int jc = tid >> 6;

    for (int i = tid; i < T_; i += 512) sinfo[i] = __ldg(&info[i]);
    if (tid == 0) sinfo[T_] = make_int4(0, 0, 0, 0);
    __syncthreads();

    int4 ci = sinfo[0];
    float av = 0.f, bv = 0.f;
    if (tid < 256 && ci.x) {
        av = v[(size_t)ci.z * D_ + tid];
        if (ci.x == 2) bv = v[(size_t)ci.w * D_ + tid];
    }
    int p_prev = -1;

    for (int t = 0; t < T_; ++t) {
        int4 nx = sinfo[t + 1];
        int ty = ci.x, p = ci.y, l = ci.z, r = ci.w;

        if (tid < 256 && ty && p_prev >= 0) {
            if (l == p_prev) av = v[(size_t)l * D_ + tid];
            if (ty == 2 && r == p_prev) bv = v[(size_t)r * D_ + tid];
        }

        if (ty == 1) {
            float avc = av;
            if (tid < 256 && nx.x) {
                av = v[(size_t)nx.z * D_ + tid];
                if (nx.x == 2) bv = v[(size_t)nx.w * D_ + tid];
            }
            if (tid < 256) v[(size_t)p * D_ + tid] = avc;
            __syncthreads();
            p_prev = p;
        } else if (ty == 2) {
            if (tid < 256) {
                sa[tid] = av;
                sb[tid] = bv;
                sb[tid + 256] = bv;
            }
            __syncthreads();

            float avn = 0.f, bvn = 0.f;
            if (tid < 256 && nx.x) {
                avn = v[(size_t)nx.z * D_ + tid];
                if (nx.x == 2) bvn = v[(size_t)nx.w * D_ + tid];
            }

            float4 w = *reinterpret_cast<const float4*>(sb + jb + og);
            float c0 = 0.f, c1 = 0.f, c2 = 0.f, c3 = 0.f;
            #pragma unroll
            for (int j = 0; j < 32; j += 4) {
                float4 a4 = *reinterpret_cast<const float4*>(sa + jb + j);
                float4 n4 = *reinterpret_cast<const float4*>(sb + jb + j + og + 4);
                c0 = fmaf(a4.x, w.x,  c0); c1 = fmaf(a4.x, w.y,  c1);
                c2 = fmaf(a4.x, w.z,  c2); c3 = fmaf(a4.x, w.w,  c3);
                c0 = fmaf(a4.y, w.y,  c0); c1 = fmaf(a4.y, w.z,  c1);
                c2 = fmaf(a4.y, w.w,  c2); c3 = fmaf(a4.y, n4.x, c3);
                c0 = fmaf(a4.z, w.z,  c0); c1 = fmaf(a4.z, w.w,  c1);
                c2 = fmaf(a4.z, n4.x, c2); c3 = fmaf(a4.z, n4.y, c3);
                c0 = fmaf(a4.w, w.w,  c0); c1 = fmaf(a4.w, n4.x, c1);
                c2 = fmaf(a4.w, n4.y, c2); c3 = fmaf(a4.w, n4.z, c3);
                w = n4;
            }
            *reinterpret_cast<float4*>(&pp2[jc][og]) = make_float4(c0, c1, c2, c3);
            __syncthreads();

            float s = 0.f, c = 0.f;
            if (tid < 256) {
                c = pp2[0][tid] + pp2[1][tid] + pp2[2][tid] + pp2[3][tid]
                  + pp2[4][tid] + pp2[5][tid] + pp2[6][tid] + pp2[7][tid];
                s = c * c;
            }
            #pragma unroll
            for (int o = 16; o; o >>= 1) s += __shfl_xor_sync(0xffffffffu, s, o);
            if (lid == 0 && wid < 8) sred[wid] = s;
            __syncthreads();
            float tot = sred[0] + sred[1] + sred[2] + sred[3]
                      + sred[4] + sred[5] + sred[6] + sred[7];
            if (tid < 256) {
                float sc = 1.f / (sqrtf(tot) + EPSF);
                v[(size_t)p * D_ + tid] = c * sc;
            }
            __syncthreads();
            av = avn; bv = bvn;
            p_prev = p;
        } else {
            if (tid < 256 && nx.x) {
                av = v[(size_t)nx.z * D_ + tid];
                if (nx.x == 2) bv = v[(size_t)nx.w * D_ + tid];
            }
            p_prev = -1;
        }
        ci = nx;
    }
}

// ---------------------------------------------------------------------------
// Stage 2b: convert composed node vectors fp32 -> fp16 hi/lo
// ---------------------------------------------------------------------------
__global__ void k_convA(int n4) {
    const float4* src = reinterpret_cast<const float4*>(g_v);
    uint2* ah = reinterpret_cast<uint2*>(g_Ah);
    uint2* al = reinterpret_cast<uint2*>(g_Al);
    int i = blockIdx.x * blockDim.x + threadIdx.x;
    int stride = gridDim.x * blockDim.x;
    for (; i < n4; i += stride) {
        float4 x = src[i];
        __half h0 = __float2half_rn(x.x), h1 = __float2half_rn(x.y);
        __half h2 = __float2half_rn(x.z), h3 = __float2half_rn(x.w);
        __half l0 = __float2half_rn(x.x - __half2float(h0));
        __half l1 = __float2half_rn(x.y - __half2float(h1));
        __half l2 = __float2half_rn(x.z - __half2float(h2));
        __half l3 = __float2half_rn(x.w - __half2float(h3));
        __half2 hA = {h0, h1}, hB = {h2, h3}, lA = {l0, l1}, lB = {l2, l3};
        ah[i] = make_uint2(*reinterpret_cast<uint32_t*>(&hA),
                           *reinterpret_cast<uint32_t*>(&hB));
        al[i] = make_uint2(*reinterpret_cast<uint32_t*>(&lA),
                           *reinterpret_cast<uint32_t*>(&lB));
    }
}

// ---------------------------------------------------------------------------
// Stage 3: WMMA fp16 2-term GEMM:  out = (Ah + Al) * Bh^T + bias
// Grid (1023, 4): CTA = 128 M x 128 N.  8 warps, warp = 32 M x 64 N.
// K chunked by 64, cp.async double-buffered.  2 mma terms per tile pair
// (was 3 bf16 terms) -> 2/3 the HMMA instruction count.
// ---------------------------------------------------------------------------
#define SLD 80      // fp16 smem leading dim (160 B rows, 256-bit aligned)
#define TLD 136     // f32 epilogue leading dim (544 B rows, 256-bit aligned)

struct SmemGemm {
    __half Ah[128][SLD];
    __half Al[128][SLD];
    __half Bh[128][SLD];
};
#define SMEM_GEMM_BYTES (2 * (int)sizeof(SmemGemm))   // 122880 B

__device__ __forceinline__ void gemm_load_chunk(SmemGemm* sm, int m0, int n0,
                                                int ch, int lrow, int lcol) {
    int k0 = ch * 64;
    const __half* ga = g_Ah + (size_t)(m0 + lrow) * D_ + k0 + lcol;
    const __half* gA = g_Al + (size_t)(m0 + lrow) * D_ + k0 + lcol;
    const __half* gb = g_Wh + (size_t)(n0 + lrow) * D_ + k0 + lcol;
    #pragma unroll
    for (int u = 0; u < 4; ++u) {
        cp16(&sm->Ah[lrow][lcol + u * 8], ga + u * 8);
        cp16(&sm->Al[lrow][lcol + u * 8], gA + u * 8);
        cp16(&sm->Bh[lrow][lcol + u * 8], gb + u * 8);
    }
}

__global__ void __launch_bounds__(256, 1)
k_gemm_wmma(const float* __restrict__ bias, float* __restrict__ out)
{
    extern __shared__ __align__(32) char smraw[];
    SmemGemm* buf0 = reinterpret_cast<SmemGemm*>(smraw);
    SmemGemm* buf1 = reinterpret_cast<SmemGemm*>(smraw + sizeof(SmemGemm));
    float* tr = reinterpret_cast<float*>(smraw);   // reused for epilogue

    int tid = threadIdx.x;
    int wid = tid >> 5;
    int m0 = blockIdx.x * 128;
    int n0 = blockIdx.y * 128;
    int wm = wid >> 1;        // 0..3 -> 32-row slab
    int wn = wid & 1;         // 0..1 -> 64-col slab

    wmma::fragment<wmma::accumulator, 16, 16, 16, float> acc[2][4];
    #pragma unroll
    for (int i = 0; i < 2; ++i)
        #pragma unroll
        for (int j = 0; j < 4; ++j) wmma::fill_fragment(acc[i][j], 0.f);

    int lrow = tid >> 1;               // 0..127
    int lcol = (tid & 1) * 32;         // 0 or 32

    gemm_load_chunk(buf0, m0, n0, 0, lrow, lcol);
    CP_COMMIT();

    for (int ch = 0; ch < 4; ++ch) {
        SmemGemm* cur = (ch & 1) ? buf1 : buf0;
        if (ch < 3) {
            SmemGemm* nxt = (ch & 1) ? buf0 : buf1;
            gemm_load_chunk(nxt, m0, n0, ch + 1, lrow, lcol);
            CP_COMMIT();
            CP_WAIT1();
        } else {
            CP_WAIT0();
        }
        __syncthreads();

        #pragma unroll
        for (int kk = 0; kk < 4; ++kk) {
            int k = kk * 16;
            wmma::fragment<wmma::matrix_a, 16, 16, 16, __half, wmma::row_major> fah[2], fal[2];
            wmma::fragment<wmma::matrix_b, 16, 16, 16, __half, wmma::col_major> fbh[4];
            #pragma unroll
            for (int i = 0; i < 2; ++i) {
                wmma::load_matrix_sync(fah[i], &cur->Ah[wm * 32 + i * 16][k], SLD);
                wmma::load_matrix_sync(fal[i], &cur->Al[wm * 32 + i * 16][k], SLD);
            }
            #pragma unroll
            for (int j = 0; j < 4; ++j)
                wmma::load_matrix_sync(fbh[j], &cur->Bh[wn * 64 + j * 16][k], SLD);
            // 2 terms, term-major (independent accumulators back-to-back)
            #pragma unroll
            for (int i = 0; i < 2; ++i)
                #pragma unroll
                for (int j = 0; j < 4; ++j)
                    wmma::mma_sync(acc[i][j], fah[i], fbh[j], acc[i][j]);
            #pragma unroll
            for (int i = 0; i < 2; ++i)
                #pragma unroll
                for (int j = 0; j < 4; ++j)
                    wmma::mma_sync(acc[i][j], fal[i], fbh[j], acc[i][j]);
        }
        __syncthreads();
    }

    // epilogue: fragments -> smem -> coalesced global with bias
    #pragma unroll
    for (int i = 0; i < 2; ++i)
        #pragma unroll
        for (int j = 0; j < 4; ++j)
            wmma::store_matrix_sync(tr + (size_t)(wm * 32 + i * 16) * TLD + wn * 64 + j * 16,
                                    acc[i][j], TLD, wmma::mem_row_major);
    __syncthreads();

    #pragma unroll 4
    for (int idx = tid; idx < 128 * 128; idx += 256) {
        int row = idx >> 7, col = idx & 127;
        int g = n0 + col;
        if (g < C_)
            out[(size_t)(m0 + row) * C_ + g] = tr[row * TLD + col] + __ldg(&bias[g]);
    }
}

// ---------------------------------------------------------------------------
// launcher
// ---------------------------------------------------------------------------
extern "C" void kernel_launch(void* const* d_in, const int* in_sizes, int n_in,
                              void* d_out, int out_size)
{
    const int*   leaf  = (const int*)  d_in[1];
    const int*   cmask = (const int*)  d_in[2];
    const int*   cinfo = (const int*)  d_in[3];
    const float* emb   = (const float*)d_in[4];
    const float* W     = (const float*)d_in[5];
    const float* bias  = (const float*)d_in[6];
    float* out = (float*)d_out;

    int n4 = (B_ * N_ * D_) / 4;
    k_zero<<<8192, 256>>>(n4);
    k_scatter_norm<<<B_ * L_, D_ / 4>>>(leaf, cmask, emb);
    k_convW<<<512, 64>>>(W);
    k_compose<<<B_, 512>>>(cinfo);
    k_convA<<<8192, 256>>>(n4);

    cudaFuncSetAttribute(k_gemm_wmma, cudaFuncAttributeMaxDynamicSharedMemorySize,
                         SMEM_GEMM_BYTES);
    dim3 ggrid(1023, 4);
    k_gemm_wmma<<<ggrid, 256, SMEM_GEMM_BYTES>>>(bias, out);
}